// round 5
// baseline (speedup 1.0000x reference)
#include <cuda_runtime.h>
#include <cstdint>

// ---------------------------------------------------------------------------
// NeRF fused forward. One block = 64 points, 256 threads, fully fused MLP.
// Activations in SMEM transposed [k][m] (stride SA=64). Weights streamed from
// L2 into SMEM via cp.async, double-buffered KC=32-row chunks.
// FP32 math throughout via packed fma.rn.f32x2 (2 MAC/instr).
// ---------------------------------------------------------------------------

namespace {

constexpr int TM       = 64;    // points per block
constexpr int NTHREADS = 256;
constexpr int KC       = 32;    // weight K-chunk rows
constexpr int SA       = 64;    // activation m-stride (floats)

// SMEM layout (float offsets)
constexpr int OFF_A0  = 0;
constexpr int OFF_A1  = OFF_A0  + 256 * SA;   // 16384
constexpr int OFF_PEX = OFF_A1  + 256 * SA;   // 32768
constexpr int OFF_PED = OFF_PEX + 64 * SA;    // 36864
constexpr int OFF_WB  = OFF_PED + 40 * SA;    // 39424
constexpr int SMEM_FLOATS = OFF_WB + 2 * KC * 256;  // 55808
constexpr int SMEM_BYTES  = SMEM_FLOATS * 4;        // 223232 < 232448 limit

__device__ __forceinline__ unsigned long long ffma2(unsigned long long a,
                                                    unsigned long long b,
                                                    unsigned long long c) {
    unsigned long long d;
    asm("fma.rn.f32x2 %0, %1, %2, %3;" : "=l"(d) : "l"(a), "l"(b), "l"(c));
    return d;
}
__device__ __forceinline__ unsigned long long pack2(float lo, float hi) {
    unsigned long long d;
    asm("mov.b64 %0, {%1, %2};" : "=l"(d) : "f"(lo), "f"(hi));
    return d;
}
__device__ __forceinline__ void unpack2(unsigned long long v, float& lo, float& hi) {
    asm("mov.b64 {%0, %1}, %2;" : "=f"(lo), "=f"(hi) : "l"(v));
}
__device__ __forceinline__ void cp_async16(uint32_t saddr, const void* gaddr) {
    asm volatile("cp.async.cg.shared.global [%0], [%1], 16;" :: "r"(saddr), "l"(gaddr));
}
__device__ __forceinline__ void cp_commit() {
    asm volatile("cp.async.commit_group;" ::: "memory");
}
template <int n> __device__ __forceinline__ void cp_wait() {
    asm volatile("cp.async.wait_group %0;" :: "n"(n) : "memory");
}

// Accurate sin/cos: double range reduction, then device sinf/cosf on |r|<=pi.
__device__ __forceinline__ void sincos_red(float a, float& s, float& c) {
    double ad = (double)a;
    double k  = rint(ad * 0.15915494309189535);           // 1/(2*pi)
    float rf  = (float)fma(k, -6.283185307179586, ad);    // a - k*2pi
    s = sinf(rf);
    c = cosf(rf);
}

struct KParams {
    const float* x;
    const float* dir;
    const float* g1W[5]; const float* g1b[5];
    const float* g2W[3]; const float* g2b[3];
    const float* c0W;  const float* c0b;
    const float* c1W;  const float* c1b;
    const float* sigW; const float* sigb;
    float* out;
};

// One linear layer: dest[n][m] = act( sum_k A[k][m]*W[k][n] + bias[n] ).
// Input may be a concat of two activation tensors (A_a rows [0,K_a), A_b rows
// [K_a, K_a+K_b)); W holds all K_a+K_b rows contiguously.
__device__ void run_layer(float* smem, int tid,
                          const float* A_a, int K_a,
                          const float* A_b, int K_b,
                          const float* W, const float* bias,
                          float* dest, bool relu)
{
    const int ni = tid & 15;
    const int mi = tid >> 4;
    const int m0 = mi << 2;     // 4 m per thread
    const int n0 = ni << 1;     // n pairs: {32j + 2ni, +1}

    float* WB = smem + OFF_WB;
    const uint32_t wb_s = (uint32_t)__cvta_generic_to_shared(WB);

    unsigned long long acc[4][8];
#pragma unroll
    for (int j = 0; j < 8; ++j) {
        unsigned long long b2 = *(const unsigned long long*)(bias + j * 32 + n0);
        acc[0][j] = b2; acc[1][j] = b2; acc[2][j] = b2; acc[3][j] = b2;
    }

#pragma unroll 1
    for (int p = 0; p < 2; ++p) {
        const float* A     = (p == 0) ? A_a : A_b;
        const int    K     = (p == 0) ? K_a : K_b;
        const int    rowOff= (p == 0) ? 0   : K_a;
        if (K == 0) continue;
        const float* Wp = W + (size_t)rowOff * 256;
        const int nch = (K + KC - 1) / KC;

        // stage chunk 0 into buf 0
        {
#pragma unroll
            for (int i = 0; i < 8; ++i) {
                int idx4 = i * NTHREADS + tid;     // 16B-unit index in chunk
                int fidx = idx4 * 4;               // float index in W part
                if (fidx < K * 256)
                    cp_async16(wb_s + (uint32_t)(idx4 * 4) * 4u, Wp + fidx);
            }
            cp_commit();
        }

#pragma unroll 1
        for (int c = 0; c < nch; ++c) {
            if (c + 1 < nch) {
                const int buf = (c + 1) & 1;
                const int cs  = (c + 1) * KC;
#pragma unroll
                for (int i = 0; i < 8; ++i) {
                    int idx4 = i * NTHREADS + tid;
                    int fidx = cs * 256 + idx4 * 4;
                    if (fidx < K * 256)
                        cp_async16(wb_s + (uint32_t)(buf * (KC * 256) + idx4 * 4) * 4u,
                                   Wp + fidx);
                }
                cp_commit();
                cp_wait<1>();     // current chunk's copies done
            } else {
                cp_wait<0>();
            }
            __syncthreads();

            const int cs  = c * KC;
            const int rem = K - cs;
            const int cnt = rem < KC ? rem : KC;
            const float* WBb  = WB + (c & 1) * (KC * 256);
            const float* Arow = A + cs * SA + m0;

#pragma unroll 2
            for (int kk = 0; kk < cnt; ++kk) {
                float4 a4 = *(const float4*)(Arow + kk * SA);
                unsigned long long a0v = pack2(a4.x, a4.x);
                unsigned long long a1v = pack2(a4.y, a4.y);
                unsigned long long a2v = pack2(a4.z, a4.z);
                unsigned long long a3v = pack2(a4.w, a4.w);
                const float* wr = WBb + kk * 256 + n0;
#pragma unroll
                for (int j = 0; j < 8; ++j) {
                    unsigned long long w2 = *(const unsigned long long*)(wr + j * 32);
                    acc[0][j] = ffma2(a0v, w2, acc[0][j]);
                    acc[1][j] = ffma2(a1v, w2, acc[1][j]);
                    acc[2][j] = ffma2(a2v, w2, acc[2][j]);
                    acc[3][j] = ffma2(a3v, w2, acc[3][j]);
                }
            }
            __syncthreads();
        }
    }

    // epilogue: activation + transposed store [n][m]
#pragma unroll
    for (int j = 0; j < 8; ++j) {
        const int n = j * 32 + n0;
#pragma unroll
        for (int m = 0; m < 4; ++m) {
            float lo, hi;
            unpack2(acc[m][j], lo, hi);
            if (relu) { lo = fmaxf(lo, 0.f); hi = fmaxf(hi, 0.f); }
            dest[n * SA + m0 + m]       = lo;
            dest[(n + 1) * SA + m0 + m] = hi;
        }
    }
    __syncthreads();
}

__global__ __launch_bounds__(NTHREADS, 1)
void nerf_kernel(KParams p)
{
    extern __shared__ float smem[];
    const int tid = threadIdx.x;
    float* A0  = smem + OFF_A0;
    float* A1  = smem + OFF_A1;
    float* PEX = smem + OFF_PEX;
    float* PED = smem + OFF_PED;

    // ---- positional encoding: [x, sin(2^l x_c), cos(2^l x_c), ...] ----
    // feature index: 0..2 = x ; 3 + 6l + t*3 + c  (t: 0=sin, 1=cos)
    if (tid < 192) {
        const int m    = tid & 63;
        const int comp = tid >> 6;           // 0..2
        const int gm   = blockIdx.x * TM + m;
        const float xv = p.x[gm * 3 + comp];
        const float dv = p.dir[gm * 3 + comp];
        PEX[comp * SA + m] = xv;
        PED[comp * SA + m] = dv;
        float f = 1.f;
#pragma unroll
        for (int l = 0; l < 10; ++l) {
            float s, c;
            sincos_red(xv * f, s, c);
            PEX[(3 + 6 * l + comp) * SA + m]     = s;
            PEX[(3 + 6 * l + 3 + comp) * SA + m] = c;
            if (l < 6) {
                sincos_red(dv * f, s, c);
                PED[(3 + 6 * l + comp) * SA + m]     = s;
                PED[(3 + 6 * l + 3 + comp) * SA + m] = c;
            }
            f *= 2.f;
        }
    }
    __syncthreads();

    // ---- MLP chain ----
    run_layer(smem, tid, PEX, 63, nullptr, 0,   p.g1W[0], p.g1b[0], A0, true);
    run_layer(smem, tid, A0, 256, nullptr, 0,   p.g1W[1], p.g1b[1], A1, true);
    run_layer(smem, tid, A1, 256, nullptr, 0,   p.g1W[2], p.g1b[2], A0, true);
    run_layer(smem, tid, A0, 256, nullptr, 0,   p.g1W[3], p.g1b[3], A1, true);
    run_layer(smem, tid, A1, 256, nullptr, 0,   p.g1W[4], p.g1b[4], A0, false); // features1 -> A0
    run_layer(smem, tid, PEX, 63, A0, 256,      p.g2W[0], p.g2b[0], A1, true);
    run_layer(smem, tid, A1, 256, nullptr, 0,   p.g2W[1], p.g2b[1], A0, true);
    run_layer(smem, tid, A0, 256, nullptr, 0,   p.g2W[2], p.g2b[2], A1, false); // features2 -> A1
    run_layer(smem, tid, PED, 39, A1, 256,      p.c0W,    p.c0b,    A0, true);  // c hidden -> A0

    // ---- heads: rgb = A0 @ c1W[256x3] + c1b ; sigma = A1 @ sigW[256] + sigb
    {
        const int m = tid & 63;
        const int q = tid >> 6;           // k-quarter
        float r = 0.f, g = 0.f, b = 0.f, s = 0.f;
        const int k0 = q * 64;
        for (int k = k0; k < k0 + 64; ++k) {
            const float h  = A0[k * SA + m];
            const float f2 = A1[k * SA + m];
            r = fmaf(h,  __ldg(p.c1W + k * 3 + 0), r);
            g = fmaf(h,  __ldg(p.c1W + k * 3 + 1), g);
            b = fmaf(h,  __ldg(p.c1W + k * 3 + 2), b);
            s = fmaf(f2, __ldg(p.sigW + k),        s);
        }
        float4* scratch = (float4*)(smem + OFF_WB);   // WB free here
        scratch[q * 64 + m] = make_float4(r, g, b, s);
        __syncthreads();
        if (tid < 64) {
            float4 t0 = scratch[tid];
            float4 t1 = scratch[64 + tid];
            float4 t2 = scratch[128 + tid];
            float4 t3 = scratch[192 + tid];
            float4 o;
            o.x = t0.x + t1.x + t2.x + t3.x + __ldg(p.c1b + 0);
            o.y = t0.y + t1.y + t2.y + t3.y + __ldg(p.c1b + 1);
            o.z = t0.z + t1.z + t2.z + t3.z + __ldg(p.c1b + 2);
            o.w = t0.w + t1.w + t2.w + t3.w + __ldg(p.sigb);
            ((float4*)p.out)[blockIdx.x * TM + tid] = o;
        }
    }
}

} // namespace

extern "C" void kernel_launch(void* const* d_in, const int* in_sizes, int n_in,
                              void* d_out, int out_size)
{
    KParams p;
    p.x   = (const float*)d_in[0];
    p.dir = (const float*)d_in[1];
    for (int i = 0; i < 5; ++i) {
        p.g1W[i] = (const float*)d_in[2 + 2 * i];
        p.g1b[i] = (const float*)d_in[3 + 2 * i];
    }
    for (int i = 0; i < 3; ++i) {
        p.g2W[i] = (const float*)d_in[12 + 2 * i];
        p.g2b[i] = (const float*)d_in[13 + 2 * i];
    }
    p.c0W  = (const float*)d_in[18]; p.c0b  = (const float*)d_in[19];
    p.c1W  = (const float*)d_in[20]; p.c1b  = (const float*)d_in[21];
    p.sigW = (const float*)d_in[22]; p.sigb = (const float*)d_in[23];
    p.out  = (float*)d_out;

    cudaFuncSetAttribute(nerf_kernel, cudaFuncAttributeMaxDynamicSharedMemorySize,
                         SMEM_BYTES);

    const int npts = in_sizes[0] / 3;
    nerf_kernel<<<npts / TM, NTHREADS, SMEM_BYTES>>>(p);
}

// round 10
// speedup vs baseline: 3.7271x; 3.7271x over previous
#include <cuda_runtime.h>
#include <cuda_bf16.h>
#include <cstdint>

namespace {

constexpr int NCHUNK      = 70;
constexpr int CHUNK_BYTES = 32768;    // [hi 16KB][lo 16KB]; 256 n-rows x 16 words x 4B per plane

// SMEM word offsets (uint32 units)
constexpr int W_ACT_H = 0;        // 8192 words (64 rows x 128 words)
constexpr int W_ACT_L = 8192;
constexpr int W_PEX_H = 16384;    // 2048 words (64 rows x 32 words)
constexpr int W_PEX_L = 18432;
constexpr int W_PED_H = 20480;
constexpr int W_PED_L = 22528;
constexpr int W_WBUF  = 24576;    // 2 x 8192 words
constexpr int W_BIAS  = 40960;    // 9*256 floats
constexpr int W_SIGW  = 43264;    // 256 floats
constexpr int W_C1W   = 43520;    // 768 floats
constexpr int W_SIGS  = 44288;    // 64 floats
constexpr int SMEM_BYTES = (44288 + 64) * 4;   // 177408

__device__ __align__(128) unsigned char WPRE[(size_t)NCHUNK * CHUNK_BYTES];

__constant__ uint8_t CH_L[NCHUNK] = {
    0,0,
    1,1,1,1,1,1,1,1,
    2,2,2,2,2,2,2,2,
    3,3,3,3,3,3,3,3,
    4,4,4,4,4,4,4,4,
    5,5,5,5,5,5,5,5,5,5,
    6,6,6,6,6,6,6,6,
    7,7,7,7,7,7,7,7,
    8,8,8,8,8,8,8,8,8,8};
__constant__ uint16_t CH_K0[NCHUNK] = {
    0,32,
    0,32,64,96,128,160,192,224,
    0,32,64,96,128,160,192,224,
    0,32,64,96,128,160,192,224,
    0,32,64,96,128,160,192,224,
    0,32,64,96,128,160,192,224,256,288,
    0,32,64,96,128,160,192,224,
    0,32,64,96,128,160,192,224,
    0,32,64,96,128,160,192,224,256,288};
__constant__ int8_t NKS[9]    = {4,16,16,16,16,20,16,16,20};  // k-steps (16 each) per layer
__constant__ int8_t RELU_L[9] = {1,1,1,1,0,1,1,0,1};

// ---------------- helpers ----------------
__device__ __forceinline__ uint32_t smem_u32(const void* p) {
    uint32_t a;
    asm("{ .reg .u64 t; cvta.to.shared.u64 t, %1; cvt.u32.u64 %0, t; }" : "=r"(a) : "l"(p));
    return a;
}
__device__ __forceinline__ void cp_async16(uint32_t s, const void* g) {
    asm volatile("cp.async.cg.shared.global [%0], [%1], 16;" :: "r"(s), "l"(g));
}
__device__ __forceinline__ void cp_commit() { asm volatile("cp.async.commit_group;" ::: "memory"); }
template <int n> __device__ __forceinline__ void cp_wait() {
    asm volatile("cp.async.wait_group %0;" :: "n"(n) : "memory");
}

__device__ __forceinline__ void mma16816(float* c, const uint32_t* a, const uint32_t* b) {
    asm volatile("mma.sync.aligned.m16n8k16.row.col.f32.bf16.bf16.f32 "
        "{%0,%1,%2,%3}, {%4,%5,%6,%7}, {%8,%9}, {%0,%1,%2,%3};"
        : "+f"(c[0]), "+f"(c[1]), "+f"(c[2]), "+f"(c[3])
        : "r"(a[0]), "r"(a[1]), "r"(a[2]), "r"(a[3]), "r"(b[0]), "r"(b[1]));
}

// accurate sin/cos: double range reduction then fp32 sin/cos (matches fp32 ref)
__device__ __forceinline__ void sincos_red(float a, float& s, float& c) {
    double ad = (double)a;
    double k  = rint(ad * 0.15915494309189535);
    float rf  = (float)fma(k, -6.283185307179586, ad);
    s = sinf(rf); c = cosf(rf);
}

struct KPW { const float* W[9]; };
struct KP {
    const float* x; const float* dir;
    const float* b[9];
    const float* sigW; const float* sigb;
    const float* c1W;  const float* c1b;
    float* out;
};

// ---------------- weight prep: split, transpose to [n][k], swizzle, pad ----------------
__global__ void prep_kernel(KPW pw) {
    const int gc = blockIdx.x;
    const int n  = threadIdx.x;           // output col 0..255
    const int L  = CH_L[gc];
    const int k0 = CH_K0[gc];
    const float* W = pw.W[L];
    unsigned char* dst = WPRE + (size_t)gc * CHUNK_BYTES;
    const int xw = ((n >> 1) & 3) << 2;
#pragma unroll
    for (int kk = 0; kk < 32; ++kk) {
        int r = k0 + kk;
        int rr;
        if (L == 0)      rr = (r < 63) ? r : -1;
        else if (L == 5) rr = (r < 63) ? r : ((r == 63) ? -1 : r - 1);
        else if (L == 8) rr = (r < 39) ? r : ((r < 64) ? -1 : r - 25);
        else             rr = r;
        float v = (rr >= 0) ? W[(size_t)rr * 256 + n] : 0.f;
        __nv_bfloat16 h = __float2bfloat16(v);
        __nv_bfloat16 l = __float2bfloat16(v - __bfloat162float(h));
        int word = (kk >> 1) ^ xw;
        int off  = n * 64 + word * 4 + (kk & 1) * 2;
        *(uint16_t*)(dst + off)         = __bfloat16_as_ushort(h);
        *(uint16_t*)(dst + 16384 + off) = __bfloat16_as_ushort(l);
    }
}

// ---------------- main kernel ----------------
__device__ __forceinline__ void load_chunk(uint32_t dstByte, int c, int tid) {
    const unsigned char* src = WPRE + (size_t)c * CHUNK_BYTES + tid * 16;
    uint32_t d = dstByte + tid * 16;
#pragma unroll
    for (int i = 0; i < 8; ++i)
        cp_async16(d + i * 4096, src + i * 4096);
    cp_commit();
}

__device__ __forceinline__ void put_pe(uint32_t* H, uint32_t* Lp, int m, int kk, float v) {
    __nv_bfloat16 h = __float2bfloat16(v);
    __nv_bfloat16 l = __float2bfloat16(v - __bfloat162float(h));
    int off = m * 32 + ((kk >> 1) ^ ((m & 7) << 2));
    ((uint16_t*)(H  + off))[kk & 1] = __bfloat16_as_ushort(h);
    ((uint16_t*)(Lp + off))[kk & 1] = __bfloat16_as_ushort(l);
}

__global__ __launch_bounds__(256, 1) void nerf_mma(KP p) {
    extern __shared__ uint32_t sm4[];
    const int tid  = threadIdx.x;
    const int lane = tid & 31, warp = tid >> 5;
    const int g = lane >> 2, t = lane & 3;
    const int wm = warp & 1, wn = warp >> 1;       // warp grid 2(M) x 4(N)
    const int xg = g << 2;                          // A/act swizzle xor
    const int xw = ((g >> 1) & 3) << 2;             // B swizzle xor

    uint32_t* actH = sm4 + W_ACT_H;
    uint32_t* actL = sm4 + W_ACT_L;
    uint32_t* peH[2] = { sm4 + W_PEX_H, sm4 + W_PED_H };
    uint32_t* peL[2] = { sm4 + W_PEX_L, sm4 + W_PED_L };
    const uint32_t smbyte = smem_u32(sm4);
    const uint32_t wbufByte = smbyte + W_WBUF * 4;

    // kick off weight prefetch immediately
    load_chunk(wbufByte, 0, tid);
    load_chunk(wbufByte + CHUNK_BYTES, 1, tid);

    // stage biases + head weights
    float* biasS = (float*)(sm4 + W_BIAS);
    for (int i = tid; i < 9 * 256; i += 256) biasS[i] = p.b[i >> 8][i & 255];
    float* sigWS = (float*)(sm4 + W_SIGW);
    sigWS[tid] = p.sigW[tid];
    float* c1WS = (float*)(sm4 + W_C1W);
    for (int i = tid; i < 768; i += 256) c1WS[i] = p.c1W[i];
    float* sigS = (float*)(sm4 + W_SIGS);

    // zero PE planes (covers pad rows 63 / 39..63)
    for (int i = tid; i < 8192; i += 256) sm4[W_PEX_H + i] = 0;
    __syncthreads();

    // positional encoding -> bf16 hi/lo swizzled tiles
    if (tid < 192) {
        const int m = tid & 63, comp = tid >> 6;
        const int gm = blockIdx.x * 64 + m;
        const float xv = p.x[gm * 3 + comp];
        const float dv = p.dir[gm * 3 + comp];
        put_pe(peH[0], peL[0], m, comp, xv);
        put_pe(peH[1], peL[1], m, comp, dv);
        float f = 1.f;
        for (int l = 0; l < 10; ++l) {
            float s, c;
            sincos_red(xv * f, s, c);
            put_pe(peH[0], peL[0], m, 3 + 6 * l + comp, s);
            put_pe(peH[0], peL[0], m, 3 + 6 * l + 3 + comp, c);
            if (l < 6) {
                sincos_red(dv * f, s, c);
                put_pe(peH[1], peL[1], m, 3 + 6 * l + comp, s);
                put_pe(peH[1], peL[1], m, 3 + 6 * l + 3 + comp, c);
            }
            f *= 2.f;
        }
    }
    __syncthreads();

    float acc[2][8][4];
    int gc = 0;

    for (int L = 0; L < 9; ++L) {
        // init accumulators with bias
#pragma unroll
        for (int j = 0; j < 8; ++j) {
            const int n0 = L * 256 + wn * 64 + j * 8 + t * 2;
            float b0 = biasS[n0], b1 = biasS[n0 + 1];
            acc[0][j][0] = b0; acc[0][j][1] = b1; acc[0][j][2] = b0; acc[0][j][3] = b1;
            acc[1][j][0] = b0; acc[1][j][1] = b1; acc[1][j][2] = b0; acc[1][j][3] = b1;
        }

        const int nck = NKS[L] >> 1;
        const int koff = (L == 5 || L == 8) ? 4 : 0;
        for (int ck = 0; ck < nck; ++ck) {
            if (gc < NCHUNK - 1) cp_wait<1>(); else cp_wait<0>();
            __syncthreads();
            const uint32_t* Wh = sm4 + W_WBUF + (gc & 1) * 8192;
            const uint32_t* Wl = Wh + 4096;
            const uint32_t* Whg = Wh + (wn * 64 + g) * 16;
            const uint32_t* Wlg = Wl + (wn * 64 + g) * 16;

#pragma unroll
            for (int s = 0; s < 2; ++s) {
                const int ks = ck * 2 + s;
                const int b0i = (s * 8 + t) ^ xw;
                const int b1i = (s * 8 + t + 4) ^ xw;
                uint32_t bh[8][2], bl[8][2];
#pragma unroll
                for (int j = 0; j < 8; ++j) {
                    bh[j][0] = Whg[j * 128 + b0i]; bh[j][1] = Whg[j * 128 + b1i];
                    bl[j][0] = Wlg[j * 128 + b0i]; bl[j][1] = Wlg[j * 128 + b1i];
                }

                const bool pe = (L == 0) || (koff && ks < 4);
                const uint32_t* sH; const uint32_t* sL; int stride, kw;
                if (pe) {
                    const int pi = (L == 8) ? 1 : 0;
                    sH = peH[pi]; sL = peL[pi]; stride = 32; kw = ks * 8;
                } else {
                    sH = actH; sL = actL; stride = 128; kw = (ks - koff) * 8;
                }
                const int w0s = (kw + t) ^ xg, w1s = (kw + t + 4) ^ xg;
                uint32_t ah[2][4], al[2][4];
#pragma unroll
                for (int i2 = 0; i2 < 2; ++i2) {
                    const int r0 = wm * 32 + i2 * 16 + g;
                    const uint32_t* hA = sH + r0 * stride;
                    const uint32_t* lA = sL + r0 * stride;
                    ah[i2][0] = hA[w0s]; ah[i2][1] = hA[8 * stride + w0s];
                    ah[i2][2] = hA[w1s]; ah[i2][3] = hA[8 * stride + w1s];
                    al[i2][0] = lA[w0s]; al[i2][1] = lA[8 * stride + w0s];
                    al[i2][2] = lA[w1s]; al[i2][3] = lA[8 * stride + w1s];
                }
#pragma unroll
                for (int i2 = 0; i2 < 2; ++i2)
#pragma unroll
                    for (int j = 0; j < 8; ++j) {
                        mma16816(acc[i2][j], ah[i2], bh[j]);
                        mma16816(acc[i2][j], al[i2], bh[j]);
                        mma16816(acc[i2][j], ah[i2], bl[j]);
                    }
            }
            __syncthreads();
            if (gc + 2 < NCHUNK) load_chunk(wbufByte + (gc & 1) * CHUNK_BYTES, gc + 2, tid);
            ++gc;
        }

        // epilogue: bias already in, relu, bf16 hi/lo repack, in-place act store
        const bool rl = RELU_L[L];
#pragma unroll
        for (int i2 = 0; i2 < 2; ++i2) {
            const int r0 = wm * 32 + i2 * 16 + g;
#pragma unroll
            for (int j = 0; j < 8; ++j) {
                const int cw  = wn * 32 + j * 4 + t;
                const int sw_ = cw ^ xg;
                float v0 = acc[i2][j][0], v1 = acc[i2][j][1];
                float v2 = acc[i2][j][2], v3 = acc[i2][j][3];
                if (rl) { v0 = fmaxf(v0,0.f); v1 = fmaxf(v1,0.f); v2 = fmaxf(v2,0.f); v3 = fmaxf(v3,0.f); }
                uint32_t h0 = __bfloat16_as_ushort(__float2bfloat16(v0));
                uint32_t h1 = __bfloat16_as_ushort(__float2bfloat16(v1));
                uint32_t h2 = __bfloat16_as_ushort(__float2bfloat16(v2));
                uint32_t h3 = __bfloat16_as_ushort(__float2bfloat16(v3));
                float l0 = v0 - __uint_as_float(h0 << 16);
                float l1 = v1 - __uint_as_float(h1 << 16);
                float l2 = v2 - __uint_as_float(h2 << 16);
                float l3 = v3 - __uint_as_float(h3 << 16);
                actH[r0 * 128 + sw_]       = h0 | (h1 << 16);
                actH[(r0 + 8) * 128 + sw_] = h2 | (h3 << 16);
                actL[r0 * 128 + sw_] =
                    (uint32_t)__bfloat16_as_ushort(__float2bfloat16(l0)) |
                    ((uint32_t)__bfloat16_as_ushort(__float2bfloat16(l1)) << 16);
                actL[(r0 + 8) * 128 + sw_] =
                    (uint32_t)__bfloat16_as_ushort(__float2bfloat16(l2)) |
                    ((uint32_t)__bfloat16_as_ushort(__float2bfloat16(l3)) << 16);
            }
        }
        __syncthreads();

        if (L == 7) {  // sigma head on features2 (raw)
            if (tid < 64) {
                const int m = tid, x4 = (m & 7) << 2;
                float s = 0.f;
#pragma unroll 4
                for (int w = 0; w < 128; ++w) {
                    const int idx = m * 128 + (w ^ x4);
                    const uint32_t hw = actH[idx], lw = actL[idx];
                    float v0 = __uint_as_float(hw << 16) + __uint_as_float(lw << 16);
                    float v1 = __uint_as_float(hw & 0xFFFF0000u) + __uint_as_float(lw & 0xFFFF0000u);
                    s = fmaf(v0, sigWS[2 * w], fmaf(v1, sigWS[2 * w + 1], s));
                }
                sigS[m] = s;
            }
            __syncthreads();
        }
    }

    // rgb head on relu'd c-hidden (act) + output
    if (tid < 64) {
        const int m = tid, x4 = (m & 7) << 2;
        float r = 0.f, gq = 0.f, b = 0.f;
#pragma unroll 4
        for (int w = 0; w < 128; ++w) {
            const int idx = m * 128 + (w ^ x4);
            const uint32_t hw = actH[idx], lw = actL[idx];
            float v0 = __uint_as_float(hw << 16) + __uint_as_float(lw << 16);
            float v1 = __uint_as_float(hw & 0xFFFF0000u) + __uint_as_float(lw & 0xFFFF0000u);
            const float* c0 = c1WS + (2 * w) * 3;
            r  = fmaf(v0, c0[0], r);  gq = fmaf(v0, c0[1], gq);  b = fmaf(v0, c0[2], b);
            r  = fmaf(v1, c0[3], r);  gq = fmaf(v1, c0[4], gq);  b = fmaf(v1, c0[5], b);
        }
        float4 o;
        o.x = r  + __ldg(p.c1b + 0);
        o.y = gq + __ldg(p.c1b + 1);
        o.z = b  + __ldg(p.c1b + 2);
        o.w = sigS[m] + __ldg(p.sigb);
        ((float4*)p.out)[blockIdx.x * 64 + m] = o;
    }
}

} // namespace

extern "C" void kernel_launch(void* const* d_in, const int* in_sizes, int n_in,
                              void* d_out, int out_size)
{
    KPW w;
    for (int i = 0; i < 5; ++i) w.W[i] = (const float*)d_in[2 + 2 * i];
    for (int i = 0; i < 3; ++i) w.W[5 + i] = (const float*)d_in[12 + 2 * i];
    w.W[8] = (const float*)d_in[18];

    KP p;
    p.x   = (const float*)d_in[0];
    p.dir = (const float*)d_in[1];
    for (int i = 0; i < 5; ++i) p.b[i] = (const float*)d_in[3 + 2 * i];
    for (int i = 0; i < 3; ++i) p.b[5 + i] = (const float*)d_in[13 + 2 * i];
    p.b[8] = (const float*)d_in[19];
    p.c1W  = (const float*)d_in[20]; p.c1b = (const float*)d_in[21];
    p.sigW = (const float*)d_in[22]; p.sigb = (const float*)d_in[23];
    p.out  = (float*)d_out;

    cudaFuncSetAttribute(nerf_mma, cudaFuncAttributeMaxDynamicSharedMemorySize, SMEM_BYTES);

    prep_kernel<<<NCHUNK, 256>>>(w);
    const int npts = in_sizes[0] / 3;
    nerf_mma<<<npts / 64, 256, SMEM_BYTES>>>(p);
}

// round 11
// speedup vs baseline: 4.3993x; 1.1804x over previous
#include <cuda_runtime.h>
#include <cuda_bf16.h>
#include <cstdint>

namespace {

constexpr int NCHUNK      = 70;
constexpr int CHUNK_BYTES = 32768;    // [hi 16KB][lo 16KB]; 256 n-rows x 16 words x 4B per plane

// SMEM word offsets (uint32 units)
constexpr int W_ACT_H = 0;        // 16384 words (128 rows x 128 words)
constexpr int W_ACT_L = 16384;
constexpr int W_PE_H  = 32768;    // 4096 words (128 rows x 32 words), shared pe_x / pe_d
constexpr int W_PE_L  = 36864;
constexpr int W_WBUF  = 40960;    // 2 x 8192 words
constexpr int SMEM_BYTES = 57344 * 4;   // 229376 <= 232448

__device__ __align__(128) unsigned char WPRE[(size_t)NCHUNK * CHUNK_BYTES];

__constant__ uint8_t CH_L[NCHUNK] = {
    0,0,
    1,1,1,1,1,1,1,1,
    2,2,2,2,2,2,2,2,
    3,3,3,3,3,3,3,3,
    4,4,4,4,4,4,4,4,
    5,5,5,5,5,5,5,5,5,5,
    6,6,6,6,6,6,6,6,
    7,7,7,7,7,7,7,7,
    8,8,8,8,8,8,8,8,8,8};
__constant__ uint16_t CH_K0[NCHUNK] = {
    0,32,
    0,32,64,96,128,160,192,224,
    0,32,64,96,128,160,192,224,
    0,32,64,96,128,160,192,224,
    0,32,64,96,128,160,192,224,
    0,32,64,96,128,160,192,224,256,288,
    0,32,64,96,128,160,192,224,
    0,32,64,96,128,160,192,224,
    0,32,64,96,128,160,192,224,256,288};
__constant__ int8_t NKS[9]    = {4,16,16,16,16,20,16,16,20};
__constant__ int8_t RELU_L[9] = {1,1,1,1,0,1,1,0,1};

// ---------------- helpers ----------------
__device__ __forceinline__ uint32_t smem_u32(const void* p) {
    uint32_t a;
    asm("{ .reg .u64 t; cvta.to.shared.u64 t, %1; cvt.u32.u64 %0, t; }" : "=r"(a) : "l"(p));
    return a;
}
__device__ __forceinline__ void cp_async16(uint32_t s, const void* g) {
    asm volatile("cp.async.cg.shared.global [%0], [%1], 16;" :: "r"(s), "l"(g));
}
__device__ __forceinline__ void cp_commit() { asm volatile("cp.async.commit_group;" ::: "memory"); }
template <int n> __device__ __forceinline__ void cp_wait() {
    asm volatile("cp.async.wait_group %0;" :: "n"(n) : "memory");
}

__device__ __forceinline__ void mma16816(float* c, const uint32_t* a, const uint32_t* b) {
    asm volatile("mma.sync.aligned.m16n8k16.row.col.f32.bf16.bf16.f32 "
        "{%0,%1,%2,%3}, {%4,%5,%6,%7}, {%8,%9}, {%0,%1,%2,%3};"
        : "+f"(c[0]), "+f"(c[1]), "+f"(c[2]), "+f"(c[3])
        : "r"(a[0]), "r"(a[1]), "r"(a[2]), "r"(a[3]), "r"(b[0]), "r"(b[1]));
}

// accurate sin/cos: double range reduction then fp32 sin/cos (matches fp32 ref)
__device__ __forceinline__ void sincos_red(float a, float& s, float& c) {
    double ad = (double)a;
    double k  = rint(ad * 0.15915494309189535);
    float rf  = (float)fma(k, -6.283185307179586, ad);
    s = sinf(rf); c = cosf(rf);
}

struct KPW { const float* W[9]; };
struct KP {
    const float* x; const float* dir;
    const float* b[9];
    const float* sigW; const float* sigb;
    const float* c1W;  const float* c1b;
    float* out;
};

// ---------------- weight prep: split, transpose to [n][k], swizzle, pad ----------------
__global__ void prep_kernel(KPW pw) {
    const int gc = blockIdx.x;
    const int n  = threadIdx.x;
    const int L  = CH_L[gc];
    const int k0 = CH_K0[gc];
    const float* W = pw.W[L];
    unsigned char* dst = WPRE + (size_t)gc * CHUNK_BYTES;
    const int xw = ((n >> 1) & 3) << 2;
#pragma unroll
    for (int kk = 0; kk < 32; ++kk) {
        int r = k0 + kk;
        int rr;
        if (L == 0)      rr = (r < 63) ? r : -1;
        else if (L == 5) rr = (r < 63) ? r : ((r == 63) ? -1 : r - 1);
        else if (L == 8) rr = (r < 39) ? r : ((r < 64) ? -1 : r - 25);
        else             rr = r;
        float v = (rr >= 0) ? W[(size_t)rr * 256 + n] : 0.f;
        __nv_bfloat16 h = __float2bfloat16(v);
        __nv_bfloat16 l = __float2bfloat16(v - __bfloat162float(h));
        int word = (kk >> 1) ^ xw;
        int off  = n * 64 + word * 4 + (kk & 1) * 2;
        *(uint16_t*)(dst + off)         = __bfloat16_as_ushort(h);
        *(uint16_t*)(dst + 16384 + off) = __bfloat16_as_ushort(l);
    }
}

// ---------------- main kernel ----------------
__device__ __forceinline__ void load_chunk(uint32_t dstByte, int c, int tid) {
    const unsigned char* src = WPRE + (size_t)c * CHUNK_BYTES + tid * 16;
    uint32_t d = dstByte + tid * 16;
#pragma unroll
    for (int i = 0; i < 8; ++i)
        cp_async16(d + i * 4096, src + i * 4096);
    cp_commit();
}

__device__ __forceinline__ void put_pe(uint32_t* H, uint32_t* Lp, int m, int kk, float v) {
    __nv_bfloat16 h = __float2bfloat16(v);
    __nv_bfloat16 l = __float2bfloat16(v - __bfloat162float(h));
    int off = m * 32 + ((kk >> 1) ^ ((m & 7) << 2));
    ((uint16_t*)(H  + off))[kk & 1] = __bfloat16_as_ushort(h);
    ((uint16_t*)(Lp + off))[kk & 1] = __bfloat16_as_ushort(l);
}

// build PE planes (128 rows) for src (x: nlev=10, dir: nlev=6). Includes syncs.
__device__ void build_pe(uint32_t* H, uint32_t* Lp, const float* src, int nlev,
                         int base, int tid) {
    for (int i = tid; i < 4096; i += 256) { H[i] = 0; Lp[i] = 0; }
    __syncthreads();
    for (int it = tid; it < 384; it += 256) {
        const int m = it & 127, comp = it >> 7;
        const float v = src[(base + m) * 3 + comp];
        put_pe(H, Lp, m, comp, v);
        float f = 1.f;
        for (int l = 0; l < nlev; ++l) {
            float s, c;
            sincos_red(v * f, s, c);
            put_pe(H, Lp, m, 3 + 6 * l + comp, s);
            put_pe(H, Lp, m, 3 + 6 * l + 3 + comp, c);
            f *= 2.f;
        }
    }
    __syncthreads();
}

__global__ __launch_bounds__(256, 1) void nerf_mma(KP p) {
    extern __shared__ uint32_t sm4[];
    const int tid  = threadIdx.x;
    const int lane = tid & 31, warp = tid >> 5;
    const int g = lane >> 2, t = lane & 3;
    const int wm = warp & 1, wn = warp >> 1;        // warp grid 2(M) x 4(N), warp tile 64x64
    const int xg = g << 2;                           // A/act swizzle xor
    const int xw = ((g >> 1) & 3) << 2;              // B swizzle xor

    uint32_t* actH = sm4 + W_ACT_H;
    uint32_t* actL = sm4 + W_ACT_L;
    uint32_t* peH  = sm4 + W_PE_H;
    uint32_t* peL  = sm4 + W_PE_L;
    const uint32_t wbufByte = smem_u32(sm4) + W_WBUF * 4;

    // kick off weight prefetch immediately, overlap with PE build
    load_chunk(wbufByte, 0, tid);
    load_chunk(wbufByte + CHUNK_BYTES, 1, tid);

    build_pe(peH, peL, p.x, 10, blockIdx.x * 128, tid);

    float acc[4][8][4];
    float sig = 0.f;
    int gc = 0;

    for (int L = 0; L < 9; ++L) {
        // init accumulators with bias (uniform __ldg, L1-broadcast)
#pragma unroll
        for (int j = 0; j < 8; ++j) {
            const int n0 = wn * 64 + j * 8 + t * 2;
            const float b0 = __ldg(p.b[L] + n0), b1 = __ldg(p.b[L] + n0 + 1);
#pragma unroll
            for (int i2 = 0; i2 < 4; ++i2) {
                acc[i2][j][0] = b0; acc[i2][j][1] = b1;
                acc[i2][j][2] = b0; acc[i2][j][3] = b1;
            }
        }

        const int nck  = NKS[L] >> 1;
        const int koff = (L == 5 || L == 8) ? 4 : 0;
        for (int ck = 0; ck < nck; ++ck) {
            if (gc < NCHUNK - 1) cp_wait<1>(); else cp_wait<0>();
            __syncthreads();
            const uint32_t* Wh  = sm4 + W_WBUF + (gc & 1) * 8192;
            const uint32_t* Wl  = Wh + 4096;
            const uint32_t* Whg = Wh + (wn * 64 + g) * 16;
            const uint32_t* Wlg = Wl + (wn * 64 + g) * 16;

#pragma unroll
            for (int s = 0; s < 2; ++s) {
                const int ks  = ck * 2 + s;
                const int b0i = (s * 8 + t) ^ xw;
                const int b1i = (s * 8 + t + 4) ^ xw;
                uint32_t bh[8][2], bl[8][2];
#pragma unroll
                for (int j = 0; j < 8; ++j) {
                    bh[j][0] = Whg[j * 128 + b0i]; bh[j][1] = Whg[j * 128 + b1i];
                    bl[j][0] = Wlg[j * 128 + b0i]; bl[j][1] = Wlg[j * 128 + b1i];
                }

                const bool pe = (L == 0) || (koff && ks < 4);
                const uint32_t* sH; const uint32_t* sL; int stride, kw;
                if (pe) { sH = peH;  sL = peL;  stride = 32;  kw = ks * 8; }
                else    { sH = actH; sL = actL; stride = 128; kw = (ks - koff) * 8; }
                const int w0s = (kw + t) ^ xg, w1s = (kw + t + 4) ^ xg;

#pragma unroll
                for (int i2 = 0; i2 < 4; ++i2) {
                    const int r0 = wm * 64 + i2 * 16 + g;
                    const uint32_t* hA = sH + r0 * stride;
                    const uint32_t* lA = sL + r0 * stride;
                    uint32_t ah[4], al[4];
                    ah[0] = hA[w0s]; ah[1] = hA[8 * stride + w0s];
                    ah[2] = hA[w1s]; ah[3] = hA[8 * stride + w1s];
                    al[0] = lA[w0s]; al[1] = lA[8 * stride + w0s];
                    al[2] = lA[w1s]; al[3] = lA[8 * stride + w1s];
#pragma unroll
                    for (int j = 0; j < 8; ++j) {
                        mma16816(acc[i2][j], ah, bh[j]);
                        mma16816(acc[i2][j], al, bh[j]);
                        mma16816(acc[i2][j], ah, bl[j]);
                    }
                }
            }
            __syncthreads();
            if (gc + 2 < NCHUNK) load_chunk(wbufByte + (gc & 1) * CHUNK_BYTES, gc + 2, tid);
            ++gc;
        }

        // epilogue: relu, bf16 hi/lo repack, in-place act store
        const bool rl = RELU_L[L];
#pragma unroll
        for (int i2 = 0; i2 < 4; ++i2) {
            const int r0 = wm * 64 + i2 * 16 + g;
#pragma unroll
            for (int j = 0; j < 8; ++j) {
                const int cw  = wn * 32 + j * 4 + t;
                const int sw_ = cw ^ xg;
                float v0 = acc[i2][j][0], v1 = acc[i2][j][1];
                float v2 = acc[i2][j][2], v3 = acc[i2][j][3];
                if (rl) { v0 = fmaxf(v0,0.f); v1 = fmaxf(v1,0.f); v2 = fmaxf(v2,0.f); v3 = fmaxf(v3,0.f); }
                uint32_t h0 = __bfloat16_as_ushort(__float2bfloat16(v0));
                uint32_t h1 = __bfloat16_as_ushort(__float2bfloat16(v1));
                uint32_t h2 = __bfloat16_as_ushort(__float2bfloat16(v2));
                uint32_t h3 = __bfloat16_as_ushort(__float2bfloat16(v3));
                float l0 = v0 - __uint_as_float(h0 << 16);
                float l1 = v1 - __uint_as_float(h1 << 16);
                float l2 = v2 - __uint_as_float(h2 << 16);
                float l3 = v3 - __uint_as_float(h3 << 16);
                actH[r0 * 128 + sw_]       = h0 | (h1 << 16);
                actH[(r0 + 8) * 128 + sw_] = h2 | (h3 << 16);
                actL[r0 * 128 + sw_] =
                    (uint32_t)__bfloat16_as_ushort(__float2bfloat16(l0)) |
                    ((uint32_t)__bfloat16_as_ushort(__float2bfloat16(l1)) << 16);
                actL[(r0 + 8) * 128 + sw_] =
                    (uint32_t)__bfloat16_as_ushort(__float2bfloat16(l2)) |
                    ((uint32_t)__bfloat16_as_ushort(__float2bfloat16(l3)) << 16);
            }
        }
        __syncthreads();

        if (L == 5) {   // pe_x dead; rebuild planes with pe_d for L8
            build_pe(peH, peL, p.dir, 6, blockIdx.x * 128, tid);
        }

        if (L == 7 && tid < 128) {   // sigma head on features2 (raw), kept in register
            const int m = tid, x4 = (m & 7) << 2;
            float s = 0.f;
#pragma unroll 4
            for (int w = 0; w < 128; ++w) {
                const int idx = m * 128 + (w ^ x4);
                const uint32_t hw = actH[idx], lw = actL[idx];
                float v0 = __uint_as_float(hw << 16) + __uint_as_float(lw << 16);
                float v1 = __uint_as_float(hw & 0xFFFF0000u) + __uint_as_float(lw & 0xFFFF0000u);
                s = fmaf(v0, __ldg(p.sigW + 2 * w), fmaf(v1, __ldg(p.sigW + 2 * w + 1), s));
            }
            sig = s;
        }
    }

    // rgb head on relu'd c-hidden (act) + output
    if (tid < 128) {
        const int m = tid, x4 = (m & 7) << 2;
        float r = 0.f, gq = 0.f, b = 0.f;
#pragma unroll 4
        for (int w = 0; w < 128; ++w) {
            const int idx = m * 128 + (w ^ x4);
            const uint32_t hw = actH[idx], lw = actL[idx];
            float v0 = __uint_as_float(hw << 16) + __uint_as_float(lw << 16);
            float v1 = __uint_as_float(hw & 0xFFFF0000u) + __uint_as_float(lw & 0xFFFF0000u);
            const float* c0 = p.c1W + (2 * w) * 3;
            r  = fmaf(v0, __ldg(c0 + 0), r);
            gq = fmaf(v0, __ldg(c0 + 1), gq);
            b  = fmaf(v0, __ldg(c0 + 2), b);
            r  = fmaf(v1, __ldg(c0 + 3), r);
            gq = fmaf(v1, __ldg(c0 + 4), gq);
            b  = fmaf(v1, __ldg(c0 + 5), b);
        }
        float4 o;
        o.x = r  + __ldg(p.c1b + 0);
        o.y = gq + __ldg(p.c1b + 1);
        o.z = b  + __ldg(p.c1b + 2);
        o.w = sig + __ldg(p.sigb);
        ((float4*)p.out)[blockIdx.x * 128 + m] = o;
    }
}

} // namespace

extern "C" void kernel_launch(void* const* d_in, const int* in_sizes, int n_in,
                              void* d_out, int out_size)
{
    KPW w;
    for (int i = 0; i < 5; ++i) w.W[i] = (const float*)d_in[2 + 2 * i];
    for (int i = 0; i < 3; ++i) w.W[5 + i] = (const float*)d_in[12 + 2 * i];
    w.W[8] = (const float*)d_in[18];

    KP p;
    p.x   = (const float*)d_in[0];
    p.dir = (const float*)d_in[1];
    for (int i = 0; i < 5; ++i) p.b[i] = (const float*)d_in[3 + 2 * i];
    for (int i = 0; i < 3; ++i) p.b[5 + i] = (const float*)d_in[13 + 2 * i];
    p.b[8] = (const float*)d_in[19];
    p.c1W  = (const float*)d_in[20]; p.c1b = (const float*)d_in[21];
    p.sigW = (const float*)d_in[22]; p.sigb = (const float*)d_in[23];
    p.out  = (float*)d_out;

    cudaFuncSetAttribute(nerf_mma, cudaFuncAttributeMaxDynamicSharedMemorySize, SMEM_BYTES);

    prep_kernel<<<NCHUNK, 256>>>(w);
    const int npts = in_sizes[0] / 3;
    nerf_mma<<<npts / 128, 256, SMEM_BYTES>>>(p);
}